// round 2
// baseline (speedup 1.0000x reference)
#include <cuda_runtime.h>
#include <math.h>

#define Bdim 128
#define Pdim 256
#define PIXdim 256
#define Ddim 512
#define Cdim 10

#define NSTATE (Bdim*Pdim*Ddim)   // 16,777,216
#define NATTN  (Bdim*Pdim*Pdim)   // 8,388,608
#define NPART  4096

typedef unsigned long long ull;
#define SGN2 0x8000000080000000ULL

static __device__ float g_re0[NSTATE];
static __device__ float g_im0[NSTATE];
static __device__ float g_re1[NSTATE];
static __device__ float g_im1[NSTATE];
static __device__ float g_u_re[NSTATE];
static __device__ float g_u_im[NSTATE];
static __device__ float g_attn[NATTN];
static __device__ float g_pool_re[Bdim*Ddim];
static __device__ float g_pool_im[Bdim*Ddim];
static __device__ float g_cd[Ddim], g_sd[Ddim], g_cv[Ddim], g_sv[Ddim];
static __device__ double g_part_d[NPART];
static __device__ double g_part_n[NPART];
static __device__ int g_active;
static __device__ int g_cur;

// ---------------------------------------------------------------- packed f32x2 helpers
__device__ __forceinline__ ull ldp(const float* p) {
    float2 v = *reinterpret_cast<const float2*>(p);
    ull r; asm("mov.b64 %0, {%1,%2};" : "=l"(r) : "f"(v.x), "f"(v.y)); return r;
}
__device__ __forceinline__ float2 up(ull v) {
    float2 r; asm("mov.b64 {%0,%1}, %2;" : "=f"(r.x), "=f"(r.y) : "l"(v)); return r;
}
__device__ __forceinline__ void fma2(ull& d, ull a, ull b) {
    asm("fma.rn.f32x2 %0, %1, %2, %0;" : "+l"(d) : "l"(a), "l"(b));
}

// ---------------------------------------------------------------- prep
__global__ void k_prep(const float* __restrict__ qr, const float* __restrict__ kr,
                       const float* __restrict__ vr) {
    int d = threadIdx.x;
    if (d < Ddim) {
        float cq, sq, ck, sk, cv, sv;
        sincosf(qr[d], &sq, &cq);
        sincosf(kr[d], &sk, &ck);
        sincosf(vr[d], &sv, &cv);
        g_cd[d] = cq*ck + sq*sk;
        g_sd[d] = sq*ck - cq*sk;
        g_cv[d] = cv;
        g_sv[d] = sv;
    }
    if (d == 0) { g_active = 1; g_cur = 0; }
}

// ---------------------------------------------------------------- proj: state = tanh(x@Wp^T+bp) * e^{i phase}
__global__ void k_proj(const float* __restrict__ x, const float* __restrict__ Wp,
                       const float* __restrict__ bp) {
    __shared__ float As[16][68];
    __shared__ float Bs[16][68];
    const int tid = threadIdx.x;
    const int m0 = blockIdx.y * 64, n0 = blockIdx.x * 64;
    const int tm = (tid >> 4) * 4, tn = (tid & 15) * 4;
    const int lk = tid & 15, lr = tid >> 4;
    float acc[4][4] = {};
    for (int k0 = 0; k0 < PIXdim; k0 += 16) {
        #pragma unroll
        for (int i = 0; i < 4; i++) {
            As[lk][lr + 16*i] = x [(size_t)(m0 + lr + 16*i) * PIXdim + (k0 + lk)];
            Bs[lk][lr + 16*i] = Wp[(size_t)(n0 + lr + 16*i) * PIXdim + (k0 + lk)];
        }
        __syncthreads();
        #pragma unroll
        for (int kk = 0; kk < 16; kk++) {
            float a[4], b[4];
            #pragma unroll
            for (int i = 0; i < 4; i++) { a[i] = As[kk][tm+i]; b[i] = Bs[kk][tn+i]; }
            #pragma unroll
            for (int i = 0; i < 4; i++)
                #pragma unroll
                for (int j = 0; j < 4; j++)
                    acc[i][j] = fmaf(a[i], b[j], acc[i][j]);
        }
        __syncthreads();
    }
    const float PI = 3.14159265358979323846f;
    #pragma unroll
    for (int j = 0; j < 4; j++) {
        int n = n0 + tn + j;
        float freq = 1.0f / powf(10000.0f, (float)n / (float)Ddim);
        float bpv = bp[n];
        #pragma unroll
        for (int i = 0; i < 4; i++) {
            int m = m0 + tm + i;
            int p = m & (Pdim - 1);
            float t = tanhf(acc[i][j] + bpv);
            float ph = ((float)p * freq) * PI;
            float s, c;
            sincosf(ph, &s, &c);
            size_t idx = (size_t)m * Ddim + n;
            g_re0[idx] = t * c;
            g_im0[idx] = t * s;
        }
    }
}

// ---------------------------------------------------------------- QK^H real part * scale (FFMA2)
__global__ void __launch_bounds__(256, 1) k_qk() {
    __shared__ float Aqr[16][128], Aqi[16][128];
    __shared__ float Bqr[16][256], Bqi[16][256];   // duplicated pairs
    const int tid = threadIdx.x;
    const int tx = tid & 15, ty = tid >> 4;
    const int b = blockIdx.z;
    const int p0 = blockIdx.y * 128, q0 = blockIdx.x * 128;
    const float* __restrict__ sre = (g_cur ? g_re1 : g_re0) + (size_t)b * Pdim * Ddim;
    const float* __restrict__ sim = (g_cur ? g_im1 : g_im0) + (size_t)b * Pdim * Ddim;

    ull acc[4][8];
    #pragma unroll
    for (int i = 0; i < 4; i++)
        #pragma unroll
        for (int j = 0; j < 8; j++) acc[i][j] = 0ULL;

    const int fm = tid >> 1;
    const int fk = (tid & 1) * 8;

    for (int k0 = 0; k0 < Ddim; k0 += 16) {
        // A: rotated p-rows, transposed to [kk][p]
        {
            const float4* pr = reinterpret_cast<const float4*>(&sre[(size_t)(p0+fm)*Ddim + k0 + fk]);
            const float4* pi = reinterpret_cast<const float4*>(&sim[(size_t)(p0+fm)*Ddim + k0 + fk]);
            float rev[8], imv[8];
            *reinterpret_cast<float4*>(&rev[0]) = pr[0];
            *reinterpret_cast<float4*>(&rev[4]) = pr[1];
            *reinterpret_cast<float4*>(&imv[0]) = pi[0];
            *reinterpret_cast<float4*>(&imv[4]) = pi[1];
            #pragma unroll
            for (int e = 0; e < 8; e++) {
                int d = k0 + fk + e;
                float cd = g_cd[d], sd = g_sd[d];
                float re = rev[e], im = imv[e];
                Aqr[fk+e][fm] = re * cd - im * sd;
                Aqi[fk+e][fm] = re * sd + im * cd;
            }
        }
        // B: raw q-rows, transposed + duplicated to [kk][2q]
        {
            const float4* pr = reinterpret_cast<const float4*>(&sre[(size_t)(q0+fm)*Ddim + k0 + fk]);
            const float4* pi = reinterpret_cast<const float4*>(&sim[(size_t)(q0+fm)*Ddim + k0 + fk]);
            float rev[8], imv[8];
            *reinterpret_cast<float4*>(&rev[0]) = pr[0];
            *reinterpret_cast<float4*>(&rev[4]) = pr[1];
            *reinterpret_cast<float4*>(&imv[0]) = pi[0];
            *reinterpret_cast<float4*>(&imv[4]) = pi[1];
            #pragma unroll
            for (int e = 0; e < 8; e++) {
                *reinterpret_cast<float2*>(&Bqr[fk+e][2*fm]) = make_float2(rev[e], rev[e]);
                *reinterpret_cast<float2*>(&Bqi[fk+e][2*fm]) = make_float2(imv[e], imv[e]);
            }
        }
        __syncthreads();
        #pragma unroll 4
        for (int kk = 0; kk < 16; kk++) {
            ull ar2[4], ai2[4];
            #pragma unroll
            for (int pp = 0; pp < 4; pp++) {
                ar2[pp] = ldp(&Aqr[kk][ty*8 + 2*pp]);
                ai2[pp] = ldp(&Aqi[kk][ty*8 + 2*pp]);
            }
            #pragma unroll
            for (int j = 0; j < 8; j++) {
                ull brd = ldp(&Bqr[kk][2*(tx + 16*j)]);
                ull bid = ldp(&Bqi[kk][2*(tx + 16*j)]);
                #pragma unroll
                for (int pp = 0; pp < 4; pp++) {
                    fma2(acc[pp][j], ar2[pp], brd);
                    fma2(acc[pp][j], ai2[pp], bid);
                }
            }
        }
        __syncthreads();
    }
    const float SCALE = 0.3535533905932738f;  // 8/sqrt(512)
    float* out = g_attn + (size_t)b * Pdim * Pdim;
    #pragma unroll
    for (int pp = 0; pp < 4; pp++) {
        int p = p0 + ty*8 + 2*pp;
        #pragma unroll
        for (int j = 0; j < 8; j++) {
            int q = q0 + tx + 16*j;
            float2 v = up(acc[pp][j]);
            out[(size_t)p * Pdim + q]     = v.x * SCALE;
            out[(size_t)(p+1) * Pdim + q] = v.y * SCALE;
        }
    }
}

// ---------------------------------------------------------------- softmax over rows of length 256
__global__ void k_softmax() {
    const int row = blockIdx.x;
    const int tid = threadIdx.x;
    float* a = g_attn + (size_t)row * Pdim;
    float v = a[tid];
    __shared__ float red[256];
    red[tid] = v;
    __syncthreads();
    for (int s = 128; s > 0; s >>= 1) {
        if (tid < s) red[tid] = fmaxf(red[tid], red[tid + s]);
        __syncthreads();
    }
    float mx = red[0];
    __syncthreads();
    float e = expf(v - mx);
    red[tid] = e;
    __syncthreads();
    for (int s = 128; s > 0; s >>= 1) {
        if (tid < s) red[tid] += red[tid + s];
        __syncthreads();
    }
    a[tid] = e / red[0];
}

// ---------------------------------------------------------------- u = prev + e^{iv} * (attn @ state) (FFMA2)
__global__ void __launch_bounds__(256, 1) k_av() {
    __shared__ float At[16][128];
    __shared__ float Bvr[16][256], Bvi[16][256];   // duplicated pairs
    const int tid = threadIdx.x;
    const int tx = tid & 15, ty = tid >> 4;
    const int b = blockIdx.z;
    const int p0 = blockIdx.y * 128, d0 = blockIdx.x * 128;
    const float* __restrict__ sre = (g_cur ? g_re1 : g_re0) + (size_t)b * Pdim * Ddim;
    const float* __restrict__ sim = (g_cur ? g_im1 : g_im0) + (size_t)b * Pdim * Ddim;
    const float* __restrict__ at  = g_attn + (size_t)b * Pdim * Pdim;

    ull ar[4][8], ai[4][8];
    #pragma unroll
    for (int i = 0; i < 4; i++)
        #pragma unroll
        for (int j = 0; j < 8; j++) { ar[i][j] = 0ULL; ai[i][j] = 0ULL; }

    const int fm = tid >> 1;
    const int fk = (tid & 1) * 8;
    const int bk = tid >> 4;
    const int bn = tid & 15;

    for (int k0 = 0; k0 < Pdim; k0 += 16) {
        // A: attn rows transposed to [kk][p]
        {
            const float4* pa = reinterpret_cast<const float4*>(&at[(size_t)(p0+fm)*Pdim + k0 + fk]);
            float av[8];
            *reinterpret_cast<float4*>(&av[0]) = pa[0];
            *reinterpret_cast<float4*>(&av[4]) = pa[1];
            #pragma unroll
            for (int e = 0; e < 8; e++) At[fk+e][fm] = av[e];
        }
        // B: state rows, duplicated pairs along d
        #pragma unroll
        for (int q = 0; q < 8; q++) {
            int d = bn + 16*q;
            float vr = sre[(size_t)(k0+bk)*Ddim + d0 + d];
            float vi = sim[(size_t)(k0+bk)*Ddim + d0 + d];
            *reinterpret_cast<float2*>(&Bvr[bk][2*d]) = make_float2(vr, vr);
            *reinterpret_cast<float2*>(&Bvi[bk][2*d]) = make_float2(vi, vi);
        }
        __syncthreads();
        #pragma unroll 4
        for (int kk = 0; kk < 16; kk++) {
            ull a2[4];
            #pragma unroll
            for (int pp = 0; pp < 4; pp++)
                a2[pp] = ldp(&At[kk][ty*8 + 2*pp]);
            #pragma unroll
            for (int j = 0; j < 8; j++) {
                ull brd = ldp(&Bvr[kk][2*(tx + 16*j)]);
                ull bid = ldp(&Bvi[kk][2*(tx + 16*j)]);
                #pragma unroll
                for (int pp = 0; pp < 4; pp++) {
                    fma2(ar[pp][j], a2[pp], brd);
                    fma2(ai[pp][j], a2[pp], bid);
                }
            }
        }
        __syncthreads();
    }
    #pragma unroll
    for (int j = 0; j < 8; j++) {
        int d = d0 + tx + 16*j;
        float cv = g_cv[d], sv = g_sv[d];
        #pragma unroll
        for (int pp = 0; pp < 4; pp++) {
            int p = p0 + ty*8 + 2*pp;
            float2 trp = up(ar[pp][j]);
            float2 tip = up(ai[pp][j]);
            {
                size_t idx = (size_t)b * Pdim * Ddim + (size_t)p * Ddim + d;
                float tr = trp.x, ti = tip.x;
                g_u_re[idx] = sre[(size_t)p * Ddim + d] + cv * tr - sv * ti;
                g_u_im[idx] = sim[(size_t)p * Ddim + d] + sv * tr + cv * ti;
            }
            {
                size_t idx = (size_t)b * Pdim * Ddim + (size_t)(p+1) * Ddim + d;
                float tr = trp.y, ti = tip.y;
                g_u_re[idx] = sre[(size_t)(p+1) * Ddim + d] + cv * tr - sv * ti;
                g_u_im[idx] = sim[(size_t)(p+1) * Ddim + d] + sv * tr + cv * ti;
            }
        }
    }
}

// ---------------------------------------------------------------- new = u @ (ffr + i*ffi) (FFMA2)
__global__ void __launch_bounds__(256, 1) k_ff(const float* __restrict__ ffr,
                                               const float* __restrict__ ffi) {
    __shared__ float Aur[16][128], Aui[16][128];
    __shared__ float Bfr[16][256], Bfi[16][256];   // duplicated pairs
    const int tid = threadIdx.x;
    const int tx = tid & 15, ty = tid >> 4;
    const int m0 = blockIdx.y * 128, n0 = blockIdx.x * 128;
    float* __restrict__ nre = g_cur ? g_re0 : g_re1;
    float* __restrict__ nim = g_cur ? g_im0 : g_im1;

    ull cr[4][8], ci[4][8];
    #pragma unroll
    for (int i = 0; i < 4; i++)
        #pragma unroll
        for (int j = 0; j < 8; j++) { cr[i][j] = 0ULL; ci[i][j] = 0ULL; }

    const int fm = tid >> 1;
    const int fk = (tid & 1) * 8;
    const int bk = tid >> 4;
    const int bn = tid & 15;

    for (int k0 = 0; k0 < Ddim; k0 += 16) {
        // A: u rows transposed to [kk][m]
        {
            const float4* pr = reinterpret_cast<const float4*>(&g_u_re[(size_t)(m0+fm)*Ddim + k0 + fk]);
            const float4* pi = reinterpret_cast<const float4*>(&g_u_im[(size_t)(m0+fm)*Ddim + k0 + fk]);
            float rev[8], imv[8];
            *reinterpret_cast<float4*>(&rev[0]) = pr[0];
            *reinterpret_cast<float4*>(&rev[4]) = pr[1];
            *reinterpret_cast<float4*>(&imv[0]) = pi[0];
            *reinterpret_cast<float4*>(&imv[4]) = pi[1];
            #pragma unroll
            for (int e = 0; e < 8; e++) {
                Aur[fk+e][fm] = rev[e];
                Aui[fk+e][fm] = imv[e];
            }
        }
        // B: ff rows, duplicated pairs along n
        #pragma unroll
        for (int q = 0; q < 8; q++) {
            int n = bn + 16*q;
            float vr = ffr[(size_t)(k0+bk)*Ddim + n0 + n];
            float vi = ffi[(size_t)(k0+bk)*Ddim + n0 + n];
            *reinterpret_cast<float2*>(&Bfr[bk][2*n]) = make_float2(vr, vr);
            *reinterpret_cast<float2*>(&Bfi[bk][2*n]) = make_float2(vi, vi);
        }
        __syncthreads();
        #pragma unroll 4
        for (int kk = 0; kk < 16; kk++) {
            ull ur2[4], ui2[4], nui2[4];
            #pragma unroll
            for (int pp = 0; pp < 4; pp++) {
                ur2[pp]  = ldp(&Aur[kk][ty*8 + 2*pp]);
                ui2[pp]  = ldp(&Aui[kk][ty*8 + 2*pp]);
                nui2[pp] = ui2[pp] ^ SGN2;
            }
            #pragma unroll
            for (int j = 0; j < 8; j++) {
                ull brd = ldp(&Bfr[kk][2*(tx + 16*j)]);
                ull bid = ldp(&Bfi[kk][2*(tx + 16*j)]);
                #pragma unroll
                for (int pp = 0; pp < 4; pp++) {
                    fma2(cr[pp][j], ur2[pp],  brd);
                    fma2(cr[pp][j], nui2[pp], bid);
                    fma2(ci[pp][j], ur2[pp],  bid);
                    fma2(ci[pp][j], ui2[pp],  brd);
                }
            }
        }
        __syncthreads();
    }
    #pragma unroll
    for (int pp = 0; pp < 4; pp++) {
        int m = m0 + ty*8 + 2*pp;
        #pragma unroll
        for (int j = 0; j < 8; j++) {
            int n = n0 + tx + 16*j;
            float2 vr = up(cr[pp][j]);
            float2 vi = up(ci[pp][j]);
            nre[(size_t)m * Ddim + n]     = vr.x;
            nim[(size_t)m * Ddim + n]     = vi.x;
            nre[(size_t)(m+1) * Ddim + n] = vr.y;
            nim[(size_t)(m+1) * Ddim + n] = vi.y;
        }
    }
}

// ---------------------------------------------------------------- complex_norm over rows of length D
__global__ void k_norm() {
    float* nre = g_cur ? g_re0 : g_re1;
    float* nim = g_cur ? g_im0 : g_im1;
    const int row = blockIdx.x;
    const int tid = threadIdx.x;
    const size_t base = (size_t)row * Ddim;
    float r0 = nre[base + tid],       i0 = nim[base + tid];
    float r1 = nre[base + tid + 256], i1 = nim[base + tid + 256];
    float m0 = sqrtf(r0*r0 + i0*i0);
    float m1 = sqrtf(r1*r1 + i1*i1);
    __shared__ float s_sum[256], s_sq[256];
    s_sum[tid] = m0 + m1;
    s_sq[tid]  = m0*m0 + m1*m1;
    __syncthreads();
    for (int s = 128; s > 0; s >>= 1) {
        if (tid < s) { s_sum[tid] += s_sum[tid+s]; s_sq[tid] += s_sq[tid+s]; }
        __syncthreads();
    }
    float mean = s_sum[0] * (1.0f / 512.0f);
    float var  = (s_sq[0] - 512.0f * mean * mean) * (1.0f / 511.0f);
    var = fmaxf(var, 0.0f);
    float inv = 1.0f / (sqrtf(var) + 1e-5f);
    float sc0 = tanhf((m0 - mean) * inv) / (m0 + 1e-5f);
    float sc1 = tanhf((m1 - mean) * inv) / (m1 + 1e-5f);
    nre[base + tid]       = r0 * sc0;
    nim[base + tid]       = i0 * sc0;
    nre[base + tid + 256] = r1 * sc1;
    nim[base + tid + 256] = i1 * sc1;
}

// ---------------------------------------------------------------- diff partials (deterministic)
__global__ void k_diff() {
    const float* nre = g_cur ? g_re0 : g_re1;
    const float* nim = g_cur ? g_im0 : g_im1;
    const float* pre = g_cur ? g_re1 : g_re0;
    const float* pim = g_cur ? g_im1 : g_im0;
    const int tid = threadIdx.x;
    const size_t start = (size_t)blockIdx.x * 256 + tid;
    double ld = 0.0, lnn = 0.0;
    #pragma unroll
    for (int i = 0; i < 16; i++) {
        size_t idx = start + (size_t)i * (NPART * 256);
        float nr = nre[idx], ni = nim[idx];
        float dr = nr - pre[idx], di = ni - pim[idx];
        ld  += (double)dr * dr + (double)di * di;
        lnn += (double)nr * nr + (double)ni * ni;
    }
    __shared__ double sd[256], sn[256];
    sd[tid] = ld; sn[tid] = lnn;
    __syncthreads();
    for (int s = 128; s > 0; s >>= 1) {
        if (tid < s) { sd[tid] += sd[tid+s]; sn[tid] += sn[tid+s]; }
        __syncthreads();
    }
    if (tid == 0) { g_part_d[blockIdx.x] = sd[0]; g_part_n[blockIdx.x] = sn[0]; }
}

__global__ void k_flag() {
    const int tid = threadIdx.x;
    double ld = 0.0, lnn = 0.0;
    for (int i = tid; i < NPART; i += 256) { ld += g_part_d[i]; lnn += g_part_n[i]; }
    __shared__ double sd[256], sn[256];
    sd[tid] = ld; sn[tid] = lnn;
    __syncthreads();
    for (int s = 128; s > 0; s >>= 1) {
        if (tid < s) { sd[tid] += sd[tid+s]; sn[tid] += sn[tid+s]; }
        __syncthreads();
    }
    if (tid == 0) {
        float diff = (float)(sqrt(sd[0]) / (sqrt(sn[0]) + 1e-8));
        if (g_active) g_cur ^= 1;            // commit = buffer swap (uses pre-update active)
        if (diff < 1e-3f) g_active = 0;
    }
}

// ---------------------------------------------------------------- mean pool over P
__global__ void k_pool() {
    const float* sre = g_cur ? g_re1 : g_re0;
    const float* sim = g_cur ? g_im1 : g_im0;
    const int idx = blockIdx.x * 256 + threadIdx.x;   // b*D + d
    const int b = idx >> 9, d = idx & (Ddim - 1);
    const size_t base = (size_t)b * Pdim * Ddim + d;
    float accr = 0.0f, acci = 0.0f;
    for (int p = 0; p < Pdim; p++) {
        accr += sre[base + (size_t)p * Ddim];
        acci += sim[base + (size_t)p * Ddim];
    }
    g_pool_re[idx] = accr * (1.0f / 256.0f);
    g_pool_im[idx] = acci * (1.0f / 256.0f);
}

// ---------------------------------------------------------------- logits
__global__ void k_logits(float* __restrict__ out, const float* __restrict__ Wr,
                         const float* __restrict__ br, const float* __restrict__ Wi,
                         const float* __restrict__ bi) {
    const int b = blockIdx.x, tid = threadIdx.x;
    float pr0 = g_pool_re[b * Ddim + tid],       pi0 = g_pool_im[b * Ddim + tid];
    float pr1 = g_pool_re[b * Ddim + tid + 256], pi1 = g_pool_im[b * Ddim + tid + 256];
    __shared__ float red[256];
    for (int c = 0; c < Cdim; c++) {
        float v = pr0 * Wr[c * Ddim + tid] + pr1 * Wr[c * Ddim + tid + 256]
                + pi0 * Wi[c * Ddim + tid] + pi1 * Wi[c * Ddim + tid + 256];
        red[tid] = v;
        __syncthreads();
        for (int s = 128; s > 0; s >>= 1) {
            if (tid < s) red[tid] += red[tid+s];
            __syncthreads();
        }
        if (tid == 0) out[b * Cdim + c] = red[0] + br[c] + bi[c];
        __syncthreads();
    }
}

// ---------------------------------------------------------------- launch
extern "C" void kernel_launch(void* const* d_in, const int* in_sizes, int n_in,
                              void* d_out, int out_size) {
    const float* x   = (const float*)d_in[0];
    const float* Wp  = (const float*)d_in[1];
    const float* bp  = (const float*)d_in[2];
    const float* qr  = (const float*)d_in[3];
    const float* kr  = (const float*)d_in[4];
    const float* vr  = (const float*)d_in[5];
    const float* ffr = (const float*)d_in[6];
    const float* ffi = (const float*)d_in[7];
    const float* Wr  = (const float*)d_in[8];
    const float* br  = (const float*)d_in[9];
    const float* Wi  = (const float*)d_in[10];
    const float* bi  = (const float*)d_in[11];
    float* out = (float*)d_out;

    k_prep<<<1, 512>>>(qr, kr, vr);
    k_proj<<<dim3(Ddim/64, (Bdim*Pdim)/64), 256>>>(x, Wp, bp);
    for (int step = 0; step < 4; step++) {
        k_qk<<<dim3(Pdim/128, Pdim/128, Bdim), 256>>>();
        k_softmax<<<Bdim*Pdim, 256>>>();
        k_av<<<dim3(Ddim/128, Pdim/128, Bdim), 256>>>();
        k_ff<<<dim3(Ddim/128, (Bdim*Pdim)/128), 256>>>(ffr, ffi);
        k_norm<<<Bdim*Pdim, 256>>>();
        k_diff<<<NPART, 256>>>();
        k_flag<<<1, 256>>>();
    }
    k_pool<<<(Bdim*Ddim)/256, 256>>>();
    k_logits<<<Bdim, 256>>>(out, Wr, br, Wi, bi);
}